// round 3
// baseline (speedup 1.0000x reference)
#include <cuda_runtime.h>
#include <cuda_bf16.h>

// ---------------------------------------------------------------------------
// RxnPredictor: dual D-MPNN graph conv + mol pooling + reaction MLP
// R2: gather-sums fused into GEMM A-tile loads (no tmp round-trip).
// ---------------------------------------------------------------------------

#define MAXB 200000
#define MAXA 100000
#define HDIM 256
#define NMOLS 2048
#define NEI   10

// Static scratch. atom_h aliases g_nih (nih dead after last MP GEMM epilogue).
__device__ float g_nih [MAXB * HDIM];
__device__ float g_msgA[MAXB * HDIM];
__device__ float g_msgB[MAXB * HDIM];
__device__ float g_mol [2][NMOLS * HDIM];

// ---------------------------------------------------------------------------
// Input GEMM (dense A): C = fbonds @ Wi^T; writes nih (raw) + msg (relu).
// BM=128, BN=128, BK=16, 256 threads, 8x8 microtile.
// ---------------------------------------------------------------------------
#define BM 128
#define BN 128
#define BK 16

__global__ __launch_bounds__(256, 2)
void gemm_in_kernel(const float* __restrict__ A, const float* __restrict__ W,
                    float* __restrict__ nih, float* __restrict__ msg,
                    int M, int K)
{
    __shared__ float As[BM][BK + 1];
    __shared__ float Bs[BN][BK + 1];

    const int t  = threadIdx.x;
    const int tx = t & 15;
    const int ty = t >> 4;
    const int m0 = blockIdx.x * BM;
    const int n0 = blockIdx.y * BN;

    float acc[8][8];
#pragma unroll
    for (int i = 0; i < 8; i++)
#pragma unroll
        for (int j = 0; j < 8; j++) acc[i][j] = 0.f;

    for (int k0 = 0; k0 < K; k0 += BK) {
#pragma unroll
        for (int i = 0; i < 8; i++) {
            int idx = t + i * 256;
            int mm = idx >> 4, kk = idx & 15;
            int m = m0 + mm, k = k0 + kk;
            As[mm][kk] = (m < M && k < K) ? A[m * K + k] : 0.f;
        }
#pragma unroll
        for (int i = 0; i < 8; i++) {
            int idx = t + i * 256;
            int nn = idx >> 4, kk = idx & 15;
            int k = k0 + kk;
            Bs[nn][kk] = (k < K) ? W[(n0 + nn) * K + k] : 0.f;
        }
        __syncthreads();
#pragma unroll
        for (int kk = 0; kk < BK; kk++) {
            float a[8], b[8];
#pragma unroll
            for (int i = 0; i < 8; i++) a[i] = As[ty + i * 16][kk];
#pragma unroll
            for (int j = 0; j < 8; j++) b[j] = Bs[tx + j * 16][kk];
#pragma unroll
            for (int i = 0; i < 8; i++)
#pragma unroll
                for (int j = 0; j < 8; j++)
                    acc[i][j] = fmaf(a[i], b[j], acc[i][j]);
        }
        __syncthreads();
    }

#pragma unroll
    for (int i = 0; i < 8; i++) {
        int m = m0 + ty + i * 16;
        if (m >= M) continue;
#pragma unroll
        for (int j = 0; j < 8; j++) {
            int n = n0 + tx + j * 16;
            int o = m * HDIM + n;
            float v = acc[i][j];
            nih[o] = v;
            msg[o] = fmaxf(v, 0.f);
        }
    }
}

// ---------------------------------------------------------------------------
// Fused gather + GEMM. BM=128, BN=256 (full H), BK=16, 512 threads, 8x8 tile.
// MODE 1 (bond MP):  A[m,:] = sum_j msg_src[graph[m,j],:]      (K=256)
//                    out = relu(A @ W^T + nih)
// MODE 2 (atom out): A[m,:] = [fatoms[m,0:82] | sum_j msg_src[graph[m,j],:]]
//                    out = relu(A @ W^T + bias[n])             (K=338)
// ---------------------------------------------------------------------------
#define TBM 128
#define TBN 256
#define TBK 16

template <int MODE>
__global__ __launch_bounds__(512, 1)
void gemm_fused_kernel(const float* __restrict__ msg_src,
                       const int*   __restrict__ graph,
                       const float* __restrict__ W,
                       const float* __restrict__ extra,   // nih (M1) / fatoms (M2)
                       const float* __restrict__ bias,    // bo (M2)
                       float* __restrict__ out,
                       int M, int K, int max_nei)
{
    __shared__ float As[TBM][TBK + 1];
    __shared__ float Bs[TBN][TBK + 1];
    __shared__ int   sIdx[TBM][NEI];

    const int t  = threadIdx.x;          // 0..511
    const int tx = t & 31;               // N dir (8 cols, stride 32)
    const int ty = t >> 5;               // M dir (8 rows, stride 16)
    const int m0 = blockIdx.x * TBM;

    // cache neighbor indices for this M-tile (once per block)
    for (int i = t; i < TBM * NEI; i += 512) {
        int r = i / NEI, j = i % NEI;
        int m = m0 + r;
        sIdx[r][j] = (m < M && j < max_nei) ? graph[m * max_nei + j] : -1;
    }

    float acc[8][8];
#pragma unroll
    for (int i = 0; i < 8; i++)
#pragma unroll
        for (int j = 0; j < 8; j++) acc[i][j] = 0.f;

    __syncthreads();   // sIdx ready

    for (int k0 = 0; k0 < K; k0 += TBK) {
        // ---- A tile via fused gather ----
        if (MODE == 1) {
            // thread t: row r = t/4, float4 quad q = t%4 (covers 16 k-values)
            int r = t >> 2, q = t & 3;
            int m = m0 + r;
            float4 a4 = make_float4(0.f, 0.f, 0.f, 0.f);
            if (m < M) {
                const float4* base = (const float4*)msg_src + (k0 >> 2) + q;
#pragma unroll
                for (int j = 0; j < NEI; j++) {
                    int s = sIdx[r][j];
                    if (s >= 0) {
                        float4 v = base[s * (HDIM / 4)];
                        a4.x += v.x; a4.y += v.y; a4.z += v.z; a4.w += v.w;
                    }
                }
            }
            As[r][q * 4 + 0] = a4.x;
            As[r][q * 4 + 1] = a4.y;
            As[r][q * 4 + 2] = a4.z;
            As[r][q * 4 + 3] = a4.w;
        } else {
            // scalar gather (handles the k=82 concat boundary)
#pragma unroll
            for (int i = 0; i < 4; i++) {
                int idx = t + i * 512;
                int mm = idx >> 4, kk = idx & 15;
                int m = m0 + mm, k = k0 + kk;
                float v = 0.f;
                if (m < M && k < K) {
                    if (k < 82) {
                        v = extra[m * 82 + k];
                    } else {
                        int kg = k - 82;
#pragma unroll
                        for (int j = 0; j < NEI; j++) {
                            int s = sIdx[mm][j];
                            if (s >= 0) v += msg_src[s * HDIM + kg];
                        }
                    }
                }
                As[mm][kk] = v;
            }
        }
        // ---- B tile: Bs[n][k] = W[n*K + k0+k], n = 0..255 ----
#pragma unroll
        for (int i = 0; i < 8; i++) {
            int idx = t + i * 512;
            int nn = idx >> 4, kk = idx & 15;
            int k = k0 + kk;
            Bs[nn][kk] = (k < K) ? W[nn * K + k] : 0.f;
        }
        __syncthreads();
#pragma unroll
        for (int kk = 0; kk < TBK; kk++) {
            float a[8], b[8];
#pragma unroll
            for (int i = 0; i < 8; i++) a[i] = As[ty + i * 16][kk];
#pragma unroll
            for (int j = 0; j < 8; j++) b[j] = Bs[tx + j * 32][kk];
#pragma unroll
            for (int i = 0; i < 8; i++)
#pragma unroll
                for (int j = 0; j < 8; j++)
                    acc[i][j] = fmaf(a[i], b[j], acc[i][j]);
        }
        __syncthreads();
    }

    // ---- epilogue ----
#pragma unroll
    for (int i = 0; i < 8; i++) {
        int m = m0 + ty + i * 16;
        if (m >= M) continue;
#pragma unroll
        for (int j = 0; j < 8; j++) {
            int n = tx + j * 32;
            int o = m * HDIM + n;
            float v = acc[i][j];
            if (MODE == 1) out[o] = fmaxf(v + extra[o], 0.f);
            else           out[o] = fmaxf(v + bias[n], 0.f);
        }
    }
}

// ---------------------------------------------------------------------------
// Segment sum over sorted mol_idx. One block per molecule, 256 threads.
// ---------------------------------------------------------------------------
__global__ void segsum_kernel(const float* __restrict__ atom_h,
                              const int* __restrict__ mol_idx,
                              float* __restrict__ mol_h, int n_atoms)
{
    const int m = blockIdx.x;
    const int t = threadIdx.x;
    int lo = 0, hi = n_atoms;
    while (lo < hi) { int mid = (lo + hi) >> 1; if (mol_idx[mid] < m) lo = mid + 1; else hi = mid; }
    int start = lo;
    hi = n_atoms;
    while (lo < hi) { int mid = (lo + hi) >> 1; if (mol_idx[mid] <= m) lo = mid + 1; else hi = mid; }
    int end = lo;
    float acc = 0.f;
    for (int a = start; a < end; a++) acc += atom_h[a * HDIM + t];
    mol_h[m * HDIM + t] = acc;
}

// ---------------------------------------------------------------------------
// Final MLP: out[m] = relu((tgt-src) @ Wrh^T + brh) @ Wro^T + bro
// ---------------------------------------------------------------------------
__global__ void rxn_kernel(const float* __restrict__ src_mol,
                           const float* __restrict__ tgt_mol,
                           const float* __restrict__ Wrh,
                           const float* __restrict__ brh,
                           const float* __restrict__ Wro,
                           const float* __restrict__ bro,
                           float* __restrict__ out)
{
    __shared__ float diff[HDIM];
    __shared__ float red[HDIM];
    const int m = blockIdx.x;
    const int t = threadIdx.x;
    diff[t] = tgt_mol[m * HDIM + t] - src_mol[m * HDIM + t];
    __syncthreads();
    float s = 0.f;
    const float* wr = Wrh + t * HDIM;
#pragma unroll 8
    for (int k = 0; k < HDIM; k++) s = fmaf(diff[k], __ldg(wr + k), s);
    s = fmaxf(s + brh[t], 0.f);
    red[t] = s * Wro[t];
    __syncthreads();
    for (int o = 128; o > 0; o >>= 1) {
        if (t < o) red[t] += red[t + o];
        __syncthreads();
    }
    if (t == 0) out[m] = red[0] + bro[0];
}

// ---------------------------------------------------------------------------
// Host launcher
// ---------------------------------------------------------------------------
extern "C" void kernel_launch(void* const* d_in, const int* in_sizes, int n_in,
                              void* d_out, int out_size)
{
    const float* fatoms[2]  = { (const float*)d_in[0], (const float*)d_in[5] };
    const float* fbonds[2]  = { (const float*)d_in[1], (const float*)d_in[6] };
    const int*   agraph[2]  = { (const int*)d_in[2],   (const int*)d_in[7] };
    const int*   bgraph[2]  = { (const int*)d_in[3],   (const int*)d_in[8] };
    const int*   mol_idx[2] = { (const int*)d_in[4],   (const int*)d_in[9] };
    const float* Wi[2] = { (const float*)d_in[10], (const float*)d_in[14] };
    const float* Wh[2] = { (const float*)d_in[11], (const float*)d_in[15] };
    const float* Wo[2] = { (const float*)d_in[12], (const float*)d_in[16] };
    const float* bo[2] = { (const float*)d_in[13], (const float*)d_in[17] };
    const float* Wrh = (const float*)d_in[18];
    const float* brh = (const float*)d_in[19];
    const float* Wro = (const float*)d_in[20];
    const float* bro = (const float*)d_in[21];

    const int n_atoms = in_sizes[0] / 82;
    const int n_bonds = in_sizes[1] / 88;
    const int max_nei = in_sizes[2] / n_atoms;

    float *nih, *msgA, *msgB, *mol;
    cudaGetSymbolAddress((void**)&nih,  g_nih);
    cudaGetSymbolAddress((void**)&msgA, g_msgA);
    cudaGetSymbolAddress((void**)&msgB, g_msgB);
    cudaGetSymbolAddress((void**)&mol,  g_mol);
    float* atom_h = nih;   // alias: nih dead after last MP GEMM epilogue read

    const dim3 gIn((n_bonds + BM - 1) / BM, HDIM / BN);
    const int  gMP  = (n_bonds + TBM - 1) / TBM;
    const int  gOut = (n_atoms + TBM - 1) / TBM;

    for (int g = 0; g < 2; g++) {
        float* mol_g = mol + g * (NMOLS * HDIM);

        // nei_input_h = fbonds @ Wi^T ; msgA = relu(nih)
        gemm_in_kernel<<<gIn, 256>>>(fbonds[g], Wi[g], nih, msgA, n_bonds, 88);

        // 3 MP iterations, msg ping-pongs A->B->A->B
        float* bufs[2] = { msgA, msgB };
        int cur = 0;
        for (int d = 0; d < 3; d++) {
            gemm_fused_kernel<1><<<gMP, 512>>>(bufs[cur], bgraph[g], Wh[g],
                                               nih, nullptr, bufs[1 - cur],
                                               n_bonds, HDIM, max_nei);
            cur = 1 - cur;
        }

        // output layer: atom_h = relu([fatoms | gather(msg)] @ Wo^T + bo)
        gemm_fused_kernel<2><<<gOut, 512>>>(bufs[cur], agraph[g], Wo[g],
                                            fatoms[g], bo[g], atom_h,
                                            n_atoms, 82 + HDIM, max_nei);

        segsum_kernel<<<NMOLS, 256>>>(atom_h, mol_idx[g], mol_g, n_atoms);
    }

    rxn_kernel<<<NMOLS, 256>>>(mol, mol + NMOLS * HDIM,
                               Wrh, brh, Wro, bro, (float*)d_out);
}

// round 5
// speedup vs baseline: 1.3401x; 1.3401x over previous
#include <cuda_runtime.h>
#include <cstdint>

// ---------------------------------------------------------------------------
// RxnPredictor: dual D-MPNN graph conv + mol pooling + reaction MLP
// R4: 3xTF32 split-precision tensor-core GEMMs (fp32-level accuracy),
// fused gather in A-tile load, double-buffered smem + register prefetch.
// ---------------------------------------------------------------------------

#define MAXB  200000
#define HDIM  256
#define NMOLS 2048
#define NEI   10

__device__ float g_nih [MAXB * HDIM];
__device__ float g_msgA[MAXB * HDIM];
__device__ float g_msgB[MAXB * HDIM];
__device__ float g_mol [2][NMOLS * HDIM];

// ---------------------------------------------------------------------------
// tf32 helpers
// ---------------------------------------------------------------------------
__device__ __forceinline__ uint32_t f2tf32(float v) {
    uint32_t r;
    asm("cvt.rna.tf32.f32 %0, %1;" : "=r"(r) : "f"(v));
    return r;
}
// big/small split: big = tf32(v), small = tf32(v - big)
__device__ __forceinline__ void split_tf32(float v, uint32_t& big, uint32_t& sml) {
    big = f2tf32(v);
    sml = f2tf32(v - __uint_as_float(big));
}
__device__ __forceinline__ void mma_tf32(float* d, const uint32_t* a,
                                         uint32_t b0, uint32_t b1) {
    asm volatile(
        "mma.sync.aligned.m16n8k8.row.col.f32.tf32.tf32.f32 "
        "{%0,%1,%2,%3}, {%4,%5,%6,%7}, {%8,%9}, {%0,%1,%2,%3};"
        : "+f"(d[0]), "+f"(d[1]), "+f"(d[2]), "+f"(d[3])
        : "r"(a[0]), "r"(a[1]), "r"(a[2]), "r"(a[3]), "r"(b0), "r"(b1));
}

// ---------------------------------------------------------------------------
// 3xTF32 GEMM: C[M x 256] = epilogue(A[M x K] @ W[256 x K]^T)
// Block: 512 threads, BM=128, BN=256, BK=16. Warp grid 4(m) x 4(n),
// warp tile 32x64 = 2 m-atoms x 8 n-atoms of m16n8k8.
// MODE 0: A = src dense [M x K]; out=raw, out2=relu       (input GEMM, K=88)
// MODE 1: A[m,:] = sum_j src[graph[m,j],:]; out=relu(v+extra[m,n]) (K=256)
// MODE 2: A[m,:] = [extra[m,0:82] | gather]; out=relu(v+bias[n])   (K=338)
// ---------------------------------------------------------------------------
#define AS_STRIDE 20
#define AS_SZ (128 * AS_STRIDE)           // u32 per A sub-buffer
#define BS_SZ (256 * AS_STRIDE)           // u32 per B sub-buffer
// layout: Abig[2] | Asml[2] | Bbig[2] | Bsml[2] | sIdx
#define A_SML_OFF (2 * AS_SZ)
#define B_BIG_OFF (4 * AS_SZ)
#define B_SML_OFF (4 * AS_SZ + 2 * BS_SZ)
#define SIDX_OFF  (4 * AS_SZ + 4 * BS_SZ)
#define SMEM_U32  (SIDX_OFF + 128 * NEI)
#define SMEM_BYTES (SMEM_U32 * 4)

template <int MODE>
__global__ __launch_bounds__(512)
void tf32_gemm_kernel(const float* __restrict__ src,
                      const int*   __restrict__ graph,
                      const float* __restrict__ W,
                      const float* __restrict__ extra,  // nih (M1) / fatoms (M2)
                      const float* __restrict__ bias,   // bo (M2)
                      float* __restrict__ out,
                      float* __restrict__ out2,         // msg (M0)
                      int M, int K, int max_nei)
{
    extern __shared__ uint32_t SM[];
    int* sIdx = (int*)(SM + SIDX_OFF);

    const int t    = threadIdx.x;
    const int lane = t & 31;
    const int wid  = t >> 5;
    const int gid  = lane >> 2;       // 0..7
    const int tig  = lane & 3;        // 0..3
    const int wm0  = (wid & 3) * 32;
    const int wn0  = (wid >> 2) * 64;
    const int m0   = blockIdx.x * 128;
    const int r    = t >> 2;          // A row handled by this thread (0..127)
    const int q    = t & 3;           // A k-quad (0..3)

    const int nk = (K + 15) / 16;

    if (MODE != 0) {
        for (int i = t; i < 128 * NEI; i += 512) {
            int rr = i / NEI, j = i % NEI;
            int m = m0 + rr;
            sIdx[i] = (m < M && j < max_nei) ? graph[m * max_nei + j] : -1;
        }
    }
    __syncthreads();

    float acc[2][8][4];
#pragma unroll
    for (int a = 0; a < 2; a++)
#pragma unroll
        for (int b = 0; b < 8; b++)
#pragma unroll
            for (int c = 0; c < 4; c++) acc[a][b][c] = 0.f;

    float4 av, bv0, bv1;   // prefetch registers

    auto load_tile = [&](int kb) {
        const int k0 = kb * 16;
        // ---------------- A ----------------
        av = make_float4(0.f, 0.f, 0.f, 0.f);
        const int m = m0 + r;
        if (m < M) {
            if (MODE == 0) {
                const int k = k0 + q * 4;
                if (k + 3 < K)
                    av = *(const float4*)(src + (size_t)m * K + k);
            } else if (MODE == 1) {
                const float4* bp = (const float4*)src + (k0 >> 2) + q;
                const int* ip = sIdx + r * NEI;
                float4 v0, v1, v2, v3, v4;
#pragma unroll
                for (int w = 0; w < 2; w++) {
                    int s0 = ip[w * 5 + 0], s1 = ip[w * 5 + 1], s2 = ip[w * 5 + 2];
                    int s3 = ip[w * 5 + 3], s4 = ip[w * 5 + 4];
                    v0 = (s0 >= 0) ? bp[s0 * 64] : make_float4(0, 0, 0, 0);
                    v1 = (s1 >= 0) ? bp[s1 * 64] : make_float4(0, 0, 0, 0);
                    v2 = (s2 >= 0) ? bp[s2 * 64] : make_float4(0, 0, 0, 0);
                    v3 = (s3 >= 0) ? bp[s3 * 64] : make_float4(0, 0, 0, 0);
                    v4 = (s4 >= 0) ? bp[s4 * 64] : make_float4(0, 0, 0, 0);
                    av.x += v0.x + v1.x + v2.x + v3.x + v4.x;
                    av.y += v0.y + v1.y + v2.y + v3.y + v4.y;
                    av.z += v0.z + v1.z + v2.z + v3.z + v4.z;
                    av.w += v0.w + v1.w + v2.w + v3.w + v4.w;
                }
            } else { // MODE 2: concat [fatoms(82) | gather(256)]
                float tmpv[4];
                const int* ip = sIdx + r * NEI;
#pragma unroll
                for (int c = 0; c < 4; c++) {
                    int k = k0 + q * 4 + c;
                    float v = 0.f;
                    if (k < 82) {
                        v = extra[m * 82 + k];
                    } else if (k < K) {
                        int kg = k - 82;
#pragma unroll
                        for (int j = 0; j < NEI; j++) {
                            int s = ip[j];
                            if (s >= 0) v += src[s * HDIM + kg];
                        }
                    }
                    tmpv[c] = v;
                }
                av = make_float4(tmpv[0], tmpv[1], tmpv[2], tmpv[3]);
            }
        }
        // ---------------- B ----------------
#pragma unroll
        for (int i = 0; i < 2; i++) {
            int f  = t + i * 512;
            int nn = f >> 2;
            int qq = f & 3;
            int k  = k0 + qq * 4;
            float4 bv = make_float4(0.f, 0.f, 0.f, 0.f);
            if (MODE == 2) {
                float b0 = (k + 0 < K) ? W[nn * K + k + 0] : 0.f;
                float b1 = (k + 1 < K) ? W[nn * K + k + 1] : 0.f;
                float b2 = (k + 2 < K) ? W[nn * K + k + 2] : 0.f;
                float b3 = (k + 3 < K) ? W[nn * K + k + 3] : 0.f;
                bv = make_float4(b0, b1, b2, b3);
            } else {
                if (k + 3 < K)
                    bv = *(const float4*)(W + (size_t)nn * K + k);
            }
            if (i == 0) bv0 = bv; else bv1 = bv;
        }
    };

    auto store_tile = [&](int buf) {
        uint32_t* Ab = SM + buf * AS_SZ;
        uint32_t* As = SM + A_SML_OFF + buf * AS_SZ;
        uint32_t* Bb = SM + B_BIG_OFF + buf * BS_SZ;
        uint32_t* Bs = SM + B_SML_OFF + buf * BS_SZ;
        uint32_t bx, sx, by, sy, bz, sz, bw, sw;
        split_tf32(av.x, bx, sx); split_tf32(av.y, by, sy);
        split_tf32(av.z, bz, sz); split_tf32(av.w, bw, sw);
        *(uint4*)&Ab[r * AS_STRIDE + q * 4] = make_uint4(bx, by, bz, bw);
        *(uint4*)&As[r * AS_STRIDE + q * 4] = make_uint4(sx, sy, sz, sw);
#pragma unroll
        for (int i = 0; i < 2; i++) {
            int f  = t + i * 512;
            int nn = f >> 2;
            int qq = f & 3;
            float4 bv = (i == 0) ? bv0 : bv1;
            split_tf32(bv.x, bx, sx); split_tf32(bv.y, by, sy);
            split_tf32(bv.z, bz, sz); split_tf32(bv.w, bw, sw);
            *(uint4*)&Bb[nn * AS_STRIDE + qq * 4] = make_uint4(bx, by, bz, bw);
            *(uint4*)&Bs[nn * AS_STRIDE + qq * 4] = make_uint4(sx, sy, sz, sw);
        }
    };

    // prologue
    load_tile(0);
    store_tile(0);
    __syncthreads();

    int cur = 0;
    for (int kb = 0; kb < nk; kb++) {
        const bool pf = (kb + 1 < nk);
        if (pf) load_tile(kb + 1);

        const uint32_t* Ab = SM + cur * AS_SZ;
        const uint32_t* As = SM + A_SML_OFF + cur * AS_SZ;
        const uint32_t* Bb = SM + B_BIG_OFF + cur * BS_SZ;
        const uint32_t* Bs = SM + B_SML_OFF + cur * BS_SZ;
#pragma unroll
        for (int ka = 0; ka < 2; ka++) {
            uint32_t afb[2][4], afs[2][4];
#pragma unroll
            for (int ma = 0; ma < 2; ma++) {
                int row = wm0 + ma * 16 + gid;
                int o0 = row * AS_STRIDE + ka * 8 + tig;
                int o1 = (row + 8) * AS_STRIDE + ka * 8 + tig;
                afb[ma][0] = Ab[o0];     afb[ma][1] = Ab[o1];
                afb[ma][2] = Ab[o0 + 4]; afb[ma][3] = Ab[o1 + 4];
                afs[ma][0] = As[o0];     afs[ma][1] = As[o1];
                afs[ma][2] = As[o0 + 4]; afs[ma][3] = As[o1 + 4];
            }
#pragma unroll
            for (int na = 0; na < 8; na++) {
                int col = wn0 + na * 8 + gid;
                int ob = col * AS_STRIDE + ka * 8 + tig;
                uint32_t bb0 = Bb[ob], bb1 = Bb[ob + 4];
                uint32_t bs0 = Bs[ob], bs1 = Bs[ob + 4];
                // big*big + big*small + small*big
                mma_tf32(acc[0][na], afb[0], bb0, bb1);
                mma_tf32(acc[1][na], afb[1], bb0, bb1);
                mma_tf32(acc[0][na], afb[0], bs0, bs1);
                mma_tf32(acc[1][na], afb[1], bs0, bs1);
                mma_tf32(acc[0][na], afs[0], bb0, bb1);
                mma_tf32(acc[1][na], afs[1], bb0, bb1);
            }
        }

        if (pf) store_tile(cur ^ 1);
        __syncthreads();
        cur ^= 1;
    }

    // ---- epilogue ----
#pragma unroll
    for (int ma = 0; ma < 2; ma++) {
        int mrow0 = m0 + wm0 + ma * 16 + gid;
#pragma unroll
        for (int na = 0; na < 8; na++) {
            int n = wn0 + na * 8 + 2 * tig;
            float v0 = acc[ma][na][0], v1 = acc[ma][na][1];   // row mrow0
            float v2 = acc[ma][na][2], v3 = acc[ma][na][3];   // row mrow0+8
#pragma unroll
            for (int h = 0; h < 2; h++) {
                int m = mrow0 + h * 8;
                if (m >= M) continue;
                float a = h ? v2 : v0, b = h ? v3 : v1;
                int o = m * HDIM + n;
                if (MODE == 0) {
                    *(float2*)(out + o)  = make_float2(a, b);
                    *(float2*)(out2 + o) = make_float2(fmaxf(a, 0.f), fmaxf(b, 0.f));
                } else if (MODE == 1) {
                    float2 e = *(const float2*)(extra + o);
                    *(float2*)(out + o) =
                        make_float2(fmaxf(a + e.x, 0.f), fmaxf(b + e.y, 0.f));
                } else {
                    *(float2*)(out + o) =
                        make_float2(fmaxf(a + bias[n], 0.f), fmaxf(b + bias[n + 1], 0.f));
                }
            }
        }
    }
}

// ---------------------------------------------------------------------------
// Segment sum over sorted mol_idx. One block per molecule, 256 threads.
// ---------------------------------------------------------------------------
__global__ void segsum_kernel(const float* __restrict__ atom_h,
                              const int* __restrict__ mol_idx,
                              float* __restrict__ mol_h, int n_atoms)
{
    const int m = blockIdx.x;
    const int t = threadIdx.x;
    int lo = 0, hi = n_atoms;
    while (lo < hi) { int mid = (lo + hi) >> 1; if (mol_idx[mid] < m) lo = mid + 1; else hi = mid; }
    int start = lo;
    hi = n_atoms;
    while (lo < hi) { int mid = (lo + hi) >> 1; if (mol_idx[mid] <= m) lo = mid + 1; else hi = mid; }
    int end = lo;
    float acc = 0.f;
    for (int a = start; a < end; a++) acc += atom_h[a * HDIM + t];
    mol_h[m * HDIM + t] = acc;
}

// ---------------------------------------------------------------------------
// Final MLP: out[m] = relu((tgt-src) @ Wrh^T + brh) @ Wro^T + bro
// ---------------------------------------------------------------------------
__global__ void rxn_kernel(const float* __restrict__ src_mol,
                           const float* __restrict__ tgt_mol,
                           const float* __restrict__ Wrh,
                           const float* __restrict__ brh,
                           const float* __restrict__ Wro,
                           const float* __restrict__ bro,
                           float* __restrict__ out)
{
    __shared__ float diff[HDIM];
    __shared__ float red[HDIM];
    const int m = blockIdx.x;
    const int t = threadIdx.x;
    diff[t] = tgt_mol[m * HDIM + t] - src_mol[m * HDIM + t];
    __syncthreads();
    float s = 0.f;
    const float* wr = Wrh + t * HDIM;
#pragma unroll 8
    for (int k = 0; k < HDIM; k++) s = fmaf(diff[k], __ldg(wr + k), s);
    s = fmaxf(s + brh[t], 0.f);
    red[t] = s * Wro[t];
    __syncthreads();
    for (int o = 128; o > 0; o >>= 1) {
        if (t < o) red[t] += red[t + o];
        __syncthreads();
    }
    if (t == 0) out[m] = red[0] + bro[0];
}

// ---------------------------------------------------------------------------
// Host launcher
// ---------------------------------------------------------------------------
extern "C" void kernel_launch(void* const* d_in, const int* in_sizes, int n_in,
                              void* d_out, int out_size)
{
    const float* fatoms[2]  = { (const float*)d_in[0], (const float*)d_in[5] };
    const float* fbonds[2]  = { (const float*)d_in[1], (const float*)d_in[6] };
    const int*   agraph[2]  = { (const int*)d_in[2],   (const int*)d_in[7] };
    const int*   bgraph[2]  = { (const int*)d_in[3],   (const int*)d_in[8] };
    const int*   mol_idx[2] = { (const int*)d_in[4],   (const int*)d_in[9] };
    const float* Wi[2] = { (const float*)d_in[10], (const float*)d_in[14] };
    const float* Wh[2] = { (const float*)d_in[11], (const float*)d_in[15] };
    const float* Wo[2] = { (const float*)d_in[12], (const float*)d_in[16] };
    const float* bo[2] = { (const float*)d_in[13], (const float*)d_in[17] };
    const float* Wrh = (const float*)d_in[18];
    const float* brh = (const float*)d_in[19];
    const float* Wro = (const float*)d_in[20];
    const float* bro = (const float*)d_in[21];

    const int n_atoms = in_sizes[0] / 82;
    const int n_bonds = in_sizes[1] / 88;
    const int max_nei = in_sizes[2] / n_atoms;

    cudaFuncSetAttribute(tf32_gemm_kernel<0>,
                         cudaFuncAttributeMaxDynamicSharedMemorySize, SMEM_BYTES);
    cudaFuncSetAttribute(tf32_gemm_kernel<1>,
                         cudaFuncAttributeMaxDynamicSharedMemorySize, SMEM_BYTES);
    cudaFuncSetAttribute(tf32_gemm_kernel<2>,
                         cudaFuncAttributeMaxDynamicSharedMemorySize, SMEM_BYTES);

    float *nih, *msgA, *msgB, *mol;
    cudaGetSymbolAddress((void**)&nih,  g_nih);
    cudaGetSymbolAddress((void**)&msgA, g_msgA);
    cudaGetSymbolAddress((void**)&msgB, g_msgB);
    cudaGetSymbolAddress((void**)&mol,  g_mol);
    float* atom_h = nih;   // alias: nih dead after last MP GEMM epilogue read

    const int gB = (n_bonds + 127) / 128;
    const int gA = (n_atoms + 127) / 128;

    for (int g = 0; g < 2; g++) {
        float* mol_g = mol + g * (NMOLS * HDIM);

        // nih = fbonds @ Wi^T ; msgA = relu(nih)
        tf32_gemm_kernel<0><<<gB, 512, SMEM_BYTES>>>(
            fbonds[g], nullptr, Wi[g], nullptr, nullptr,
            nih, msgA, n_bonds, 88, max_nei);

        // 3 MP iterations, msg ping-pongs A->B->A->B
        float* bufs[2] = { msgA, msgB };
        int cur = 0;
        for (int d = 0; d < 3; d++) {
            tf32_gemm_kernel<1><<<gB, 512, SMEM_BYTES>>>(
                bufs[cur], bgraph[g], Wh[g], nih, nullptr,
                bufs[1 - cur], nullptr, n_bonds, HDIM, max_nei);
            cur = 1 - cur;
        }

        // atom_h = relu([fatoms | gather(msg)] @ Wo^T + bo)
        tf32_gemm_kernel<2><<<gA, 512, SMEM_BYTES>>>(
            bufs[cur], agraph[g], Wo[g], fatoms[g], bo[g],
            atom_h, nullptr, n_atoms, 82 + HDIM, max_nei);

        segsum_kernel<<<NMOLS, 256>>>(atom_h, mol_idx[g], mol_g, n_atoms);
    }

    rxn_kernel<<<NMOLS, 256>>>(mol, mol + NMOLS * HDIM,
                               Wrh, brh, Wro, bro, (float*)d_out);
}

// round 8
// speedup vs baseline: 1.9948x; 1.4886x over previous
#include <cuda_runtime.h>
#include <cuda_fp16.h>
#include <cstdint>

// ---------------------------------------------------------------------------
// RxnPredictor: dual D-MPNN graph conv + mol pooling + reaction MLP
// R5: 3xFP16 split-precision (m16n8k16, fp32 accum) tensor-core GEMMs.
// Weights pre-split into half big/small arrays; Wo columns permuted so the
// output GEMM reuses the aligned float4 gather path.
// ---------------------------------------------------------------------------

#define MAXB  200000
#define HDIM  256
#define NMOLS 2048
#define NEI   10
#define WSTR  352          // padded K stride for pre-split weights (>=352)

__device__ float g_nih [MAXB * HDIM];
__device__ float g_msgA[MAXB * HDIM];
__device__ float g_msgB[MAXB * HDIM];
__device__ float g_mol [2][NMOLS * HDIM];
__device__ __half g_Wb[6 * 256 * WSTR];   // big halves, 6 matrices
__device__ __half g_Ws[6 * 256 * WSTR];   // small halves

// ---------------------------------------------------------------------------
// helpers
// ---------------------------------------------------------------------------
__device__ __forceinline__ uint32_t pack_h2(__half lo, __half hi) {
    __half2 h = __halves2half2(lo, hi);
    return *reinterpret_cast<uint32_t*>(&h);
}
// split (x,y) into big half2 + small half2
__device__ __forceinline__ void split2(float x, float y, uint32_t& b, uint32_t& s) {
    __half hx = __float2half_rn(x), hy = __float2half_rn(y);
    float rx = x - __half2float(hx), ry = y - __half2float(hy);
    b = pack_h2(hx, hy);
    s = pack_h2(__float2half_rn(rx), __float2half_rn(ry));
}
__device__ __forceinline__ void mma_f16(float* d, const uint32_t* a,
                                        uint32_t b0, uint32_t b1) {
    asm volatile(
        "mma.sync.aligned.m16n8k16.row.col.f32.f16.f16.f32 "
        "{%0,%1,%2,%3}, {%4,%5,%6,%7}, {%8,%9}, {%0,%1,%2,%3};"
        : "+f"(d[0]), "+f"(d[1]), "+f"(d[2]), "+f"(d[3])
        : "r"(a[0]), "r"(a[1]), "r"(a[2]), "r"(a[3]), "r"(b0), "r"(b1));
}

// ---------------------------------------------------------------------------
// Weight pre-split: W[256 x Ksrc] fp32 -> Wb/Ws[256 x WSTR] half (zero pad).
// wo_perm: output-layer column permutation [gather(256) | fatoms(82)].
// ---------------------------------------------------------------------------
__global__ void split_w_kernel(const float* __restrict__ W, int Ksrc,
                               int wo_perm, __half* __restrict__ Wb,
                               __half* __restrict__ Ws)
{
    int i = blockIdx.x * 256 + threadIdx.x;
    if (i >= 256 * WSTR) return;
    int n = i / WSTR, k = i % WSTR;
    float v = 0.f;
    if (wo_perm) {
        if (k < 256)      v = W[n * 338 + 82 + k];
        else if (k < 338) v = W[n * 338 + (k - 256)];
    } else if (k < Ksrc) {
        v = W[n * Ksrc + k];
    }
    __half hb = __float2half_rn(v);
    Wb[i] = hb;
    Ws[i] = __float2half_rn(v - __half2float(hb));
}

// ---------------------------------------------------------------------------
// 3xFP16 GEMM: C[M x 256] = epilogue(A[M x K] @ W[256 x K]^T)
// Block 512 thr, BM=128, BN=256, BK=16. Warp grid 4(m) x 4(n), warp tile
// 32x64 = 2 m-atoms x 8 n-atoms of m16n8k16.  Passes: bb + bs + sb.
// MODE 0: A = src dense [M x Kd]; out=raw, out2=relu      (input, Kd=88)
// MODE 1: A[m,:] = sum_j src[graph[m,j],:]; out=relu(v+extra) (K=256)
// MODE 2: A = [gather(256) | fatoms(82)]; out=relu(v+bias)    (K=338)
// SMEM rows: 8 data u32 (16 halves) + 4 pad = stride 12 -> conflict-free.
// ---------------------------------------------------------------------------
#define AROW 12
#define A_SZ (128 * AROW)
#define B_SZ (256 * AROW)
#define A_BIG(st) ((st) * A_SZ)
#define A_SML(st) (2 * A_SZ + (st) * A_SZ)
#define B_BIG(st) (4 * A_SZ + (st) * B_SZ)
#define B_SML(st) (4 * A_SZ + 2 * B_SZ + (st) * B_SZ)
#define SIDX_OFF  (4 * A_SZ + 4 * B_SZ)
#define SMEM_U32  (SIDX_OFF + 128 * NEI)
#define SMEM_BYTES (SMEM_U32 * 4)

template <int MODE>
__global__ __launch_bounds__(512)
void h16_gemm_kernel(const float* __restrict__ src,
                     const int*   __restrict__ graph,
                     const __half* __restrict__ Wb,
                     const __half* __restrict__ Ws,
                     const float* __restrict__ extra,  // nih (M1) / fatoms (M2)
                     const float* __restrict__ bias,   // bo (M2)
                     float* __restrict__ out,
                     float* __restrict__ out2,         // msg (M0)
                     int M, int nk, int Kd, int max_nei)
{
    extern __shared__ uint32_t SM[];
    int* sIdx = (int*)(SM + SIDX_OFF);

    const int t    = threadIdx.x;
    const int lane = t & 31;
    const int wid  = t >> 5;
    const int gid  = lane >> 2;
    const int tig  = lane & 3;
    const int wm0  = (wid & 3) * 32;
    const int wn0  = (wid >> 2) * 64;
    const int m0   = blockIdx.x * 128;
    const int r    = t >> 2;          // A row (0..127)
    const int q    = t & 3;           // A k-quad (0..3)
    const int bnn  = t >> 1;          // B row (0..255)
    const int bpt  = t & 1;           // B half-row part

    if (MODE != 0) {
        for (int i = t; i < 128 * NEI; i += 512) {
            int rr = i / NEI, j = i % NEI;
            int m = m0 + rr;
            sIdx[i] = (m < M && j < max_nei) ? graph[m * max_nei + j] : -1;
        }
    }
    __syncthreads();

    float acc[2][8][4];
#pragma unroll
    for (int a = 0; a < 2; a++)
#pragma unroll
        for (int b = 0; b < 8; b++)
#pragma unroll
            for (int c = 0; c < 4; c++) acc[a][b][c] = 0.f;

    float4 av;           // A prefetch (fp32, pre-split)
    uint4  bvb, bvs;     // B prefetch (pre-split halves)

    auto load_tile = [&](int kb) {
        const int k0 = kb * 16;
        av = make_float4(0.f, 0.f, 0.f, 0.f);
        const int m = m0 + r;
        if (m < M) {
            if (MODE == 0) {
                const int k = k0 + q * 4;
                if (k + 3 < Kd)
                    av = *(const float4*)(src + (size_t)m * Kd + k);
            } else if (MODE == 1 || (MODE == 2 && k0 < 256)) {
                const float4* bp = (const float4*)src + (k0 >> 2) + q;
                const int* ip = sIdx + r * NEI;
                float4 v0, v1, v2, v3, v4;
#pragma unroll
                for (int w = 0; w < 2; w++) {
                    int s0 = ip[w * 5 + 0], s1 = ip[w * 5 + 1], s2 = ip[w * 5 + 2];
                    int s3 = ip[w * 5 + 3], s4 = ip[w * 5 + 4];
                    v0 = (s0 >= 0) ? bp[s0 * 64] : make_float4(0, 0, 0, 0);
                    v1 = (s1 >= 0) ? bp[s1 * 64] : make_float4(0, 0, 0, 0);
                    v2 = (s2 >= 0) ? bp[s2 * 64] : make_float4(0, 0, 0, 0);
                    v3 = (s3 >= 0) ? bp[s3 * 64] : make_float4(0, 0, 0, 0);
                    v4 = (s4 >= 0) ? bp[s4 * 64] : make_float4(0, 0, 0, 0);
                    av.x += v0.x + v1.x + v2.x + v3.x + v4.x;
                    av.y += v0.y + v1.y + v2.y + v3.y + v4.y;
                    av.z += v0.z + v1.z + v2.z + v3.z + v4.z;
                    av.w += v0.w + v1.w + v2.w + v3.w + v4.w;
                }
            } else {  // MODE 2 tail: fatoms columns (k-256 < 82)
                float tmpv[4];
#pragma unroll
                for (int c = 0; c < 4; c++) {
                    int kk = k0 + q * 4 + c - 256;
                    tmpv[c] = (kk < 82) ? extra[m * 82 + kk] : 0.f;
                }
                av = make_float4(tmpv[0], tmpv[1], tmpv[2], tmpv[3]);
            }
        }
        // B: pre-split halves, padded stride -> unconditional LDG.128
        const size_t bo = (size_t)bnn * WSTR + k0 + bpt * 8;
        bvb = *(const uint4*)(Wb + bo);
        bvs = *(const uint4*)(Ws + bo);
    };

    auto store_tile = [&](int st) {
        uint32_t* Ab = SM + A_BIG(st);
        uint32_t* As = SM + A_SML(st);
        uint32_t* Bb = SM + B_BIG(st);
        uint32_t* Bs = SM + B_SML(st);
        uint32_t b0, s0, b1, s1;
        split2(av.x, av.y, b0, s0);
        split2(av.z, av.w, b1, s1);
        *(uint2*)&Ab[r * AROW + q * 2] = make_uint2(b0, b1);
        *(uint2*)&As[r * AROW + q * 2] = make_uint2(s0, s1);
        *(uint4*)&Bb[bnn * AROW + bpt * 4] = bvb;
        *(uint4*)&Bs[bnn * AROW + bpt * 4] = bvs;
    };

    load_tile(0);
    store_tile(0);
    __syncthreads();

    int cur = 0;
    for (int kb = 0; kb < nk; kb++) {
        const bool pf = (kb + 1 < nk);
        if (pf) load_tile(kb + 1);

        const uint32_t* Ab = SM + A_BIG(cur);
        const uint32_t* As = SM + A_SML(cur);
        const uint32_t* Bb = SM + B_BIG(cur);
        const uint32_t* Bs = SM + B_SML(cur);

        uint32_t afb[2][4], afs[2][4];
#pragma unroll
        for (int ma = 0; ma < 2; ma++) {
            int row = wm0 + ma * 16 + gid;
            int o0 = row * AROW + tig;
            int o1 = (row + 8) * AROW + tig;
            afb[ma][0] = Ab[o0];     afb[ma][1] = Ab[o1];
            afb[ma][2] = Ab[o0 + 4]; afb[ma][3] = Ab[o1 + 4];
            afs[ma][0] = As[o0];     afs[ma][1] = As[o1];
            afs[ma][2] = As[o0 + 4]; afs[ma][3] = As[o1 + 4];
        }
#pragma unroll
        for (int na = 0; na < 8; na++) {
            int col = wn0 + na * 8 + gid;
            int ob = col * AROW + tig;
            uint32_t bb0 = Bb[ob], bb1 = Bb[ob + 4];
            uint32_t bs0 = Bs[ob], bs1 = Bs[ob + 4];
            mma_f16(acc[0][na], afb[0], bb0, bb1);   // big*big
            mma_f16(acc[1][na], afb[1], bb0, bb1);
            mma_f16(acc[0][na], afb[0], bs0, bs1);   // big*small
            mma_f16(acc[1][na], afb[1], bs0, bs1);
            mma_f16(acc[0][na], afs[0], bb0, bb1);   // small*big
            mma_f16(acc[1][na], afs[1], bb0, bb1);
        }

        if (pf) store_tile(cur ^ 1);
        __syncthreads();
        cur ^= 1;
    }

    // ---- epilogue ----
#pragma unroll
    for (int ma = 0; ma < 2; ma++) {
        int mrow0 = m0 + wm0 + ma * 16 + gid;
#pragma unroll
        for (int na = 0; na < 8; na++) {
            int n = wn0 + na * 8 + 2 * tig;
            float v0 = acc[ma][na][0], v1 = acc[ma][na][1];
            float v2 = acc[ma][na][2], v3 = acc[ma][na][3];
#pragma unroll
            for (int h = 0; h < 2; h++) {
                int m = mrow0 + h * 8;
                if (m >= M) continue;
                float a = h ? v2 : v0, b = h ? v3 : v1;
                int o = m * HDIM + n;
                if (MODE == 0) {
                    *(float2*)(out + o)  = make_float2(a, b);
                    *(float2*)(out2 + o) = make_float2(fmaxf(a, 0.f), fmaxf(b, 0.f));
                } else if (MODE == 1) {
                    float2 e = *(const float2*)(extra + o);
                    *(float2*)(out + o) =
                        make_float2(fmaxf(a + e.x, 0.f), fmaxf(b + e.y, 0.f));
                } else {
                    *(float2*)(out + o) =
                        make_float2(fmaxf(a + bias[n], 0.f), fmaxf(b + bias[n + 1], 0.f));
                }
            }
        }
    }
}

// ---------------------------------------------------------------------------
// Segment sum over sorted mol_idx. One block per molecule, 256 threads.
// ---------------------------------------------------------------------------
__global__ void segsum_kernel(const float* __restrict__ atom_h,
                              const int* __restrict__ mol_idx,
                              float* __restrict__ mol_h, int n_atoms)
{
    const int m = blockIdx.x;
    const int t = threadIdx.x;
    int lo = 0, hi = n_atoms;
    while (lo < hi) { int mid = (lo + hi) >> 1; if (mol_idx[mid] < m) lo = mid + 1; else hi = mid; }
    int start = lo;
    hi = n_atoms;
    while (lo < hi) { int mid = (lo + hi) >> 1; if (mol_idx[mid] <= m) lo = mid + 1; else hi = mid; }
    int end = lo;
    float acc = 0.f;
    for (int a = start; a < end; a++) acc += atom_h[a * HDIM + t];
    mol_h[m * HDIM + t] = acc;
}

// ---------------------------------------------------------------------------
// Final MLP: out[m] = relu((tgt-src) @ Wrh^T + brh) @ Wro^T + bro
// ---------------------------------------------------------------------------
__global__ void rxn_kernel(const float* __restrict__ src_mol,
                           const float* __restrict__ tgt_mol,
                           const float* __restrict__ Wrh,
                           const float* __restrict__ brh,
                           const float* __restrict__ Wro,
                           const float* __restrict__ bro,
                           float* __restrict__ out)
{
    __shared__ float diff[HDIM];
    __shared__ float red[HDIM];
    const int m = blockIdx.x;
    const int t = threadIdx.x;
    diff[t] = tgt_mol[m * HDIM + t] - src_mol[m * HDIM + t];
    __syncthreads();
    float s = 0.f;
    const float* wr = Wrh + t * HDIM;
#pragma unroll 8
    for (int k = 0; k < HDIM; k++) s = fmaf(diff[k], __ldg(wr + k), s);
    s = fmaxf(s + brh[t], 0.f);
    red[t] = s * Wro[t];
    __syncthreads();
    for (int o = 128; o > 0; o >>= 1) {
        if (t < o) red[t] += red[t + o];
        __syncthreads();
    }
    if (t == 0) out[m] = red[0] + bro[0];
}

// ---------------------------------------------------------------------------
// Host launcher
// ---------------------------------------------------------------------------
extern "C" void kernel_launch(void* const* d_in, const int* in_sizes, int n_in,
                              void* d_out, int out_size)
{
    const float* fatoms[2]  = { (const float*)d_in[0], (const float*)d_in[5] };
    const float* fbonds[2]  = { (const float*)d_in[1], (const float*)d_in[6] };
    const int*   agraph[2]  = { (const int*)d_in[2],   (const int*)d_in[7] };
    const int*   bgraph[2]  = { (const int*)d_in[3],   (const int*)d_in[8] };
    const int*   mol_idx[2] = { (const int*)d_in[4],   (const int*)d_in[9] };
    const float* Wi[2] = { (const float*)d_in[10], (const float*)d_in[14] };
    const float* Wh[2] = { (const float*)d_in[11], (const float*)d_in[15] };
    const float* Wo[2] = { (const float*)d_in[12], (const float*)d_in[16] };
    const float* bo[2] = { (const float*)d_in[13], (const float*)d_in[17] };
    const float* Wrh = (const float*)d_in[18];
    const float* brh = (const float*)d_in[19];
    const float* Wro = (const float*)d_in[20];
    const float* bro = (const float*)d_in[21];

    const int n_atoms = in_sizes[0] / 82;
    const int n_bonds = in_sizes[1] / 88;
    const int max_nei = in_sizes[2] / n_atoms;

    cudaFuncSetAttribute(h16_gemm_kernel<0>,
                         cudaFuncAttributeMaxDynamicSharedMemorySize, SMEM_BYTES);
    cudaFuncSetAttribute(h16_gemm_kernel<1>,
                         cudaFuncAttributeMaxDynamicSharedMemorySize, SMEM_BYTES);
    cudaFuncSetAttribute(h16_gemm_kernel<2>,
                         cudaFuncAttributeMaxDynamicSharedMemorySize, SMEM_BYTES);

    float *nih, *msgA, *msgB, *mol;
    __half *Wbase_b, *Wbase_s;
    cudaGetSymbolAddress((void**)&nih,  g_nih);
    cudaGetSymbolAddress((void**)&msgA, g_msgA);
    cudaGetSymbolAddress((void**)&msgB, g_msgB);
    cudaGetSymbolAddress((void**)&mol,  g_mol);
    cudaGetSymbolAddress((void**)&Wbase_b, g_Wb);
    cudaGetSymbolAddress((void**)&Wbase_s, g_Ws);
    float* atom_h = nih;   // alias: nih dead after last MP GEMM epilogue read

    // pre-split weights: slots 0..5 = Wi_s, Wh_s, Wo_s, Wi_t, Wh_t, Wo_t
    const int MS = 256 * WSTR;
    const int nsplit = (256 * WSTR + 255) / 256;
    for (int g = 0; g < 2; g++) {
        split_w_kernel<<<nsplit, 256>>>(Wi[g],  88, 0, Wbase_b + (3*g+0)*MS, Wbase_s + (3*g+0)*MS);
        split_w_kernel<<<nsplit, 256>>>(Wh[g], 256, 0, Wbase_b + (3*g+1)*MS, Wbase_s + (3*g+1)*MS);
        split_w_kernel<<<nsplit, 256>>>(Wo[g], 338, 1, Wbase_b + (3*g+2)*MS, Wbase_s + (3*g+2)*MS);
    }

    const int gB = (n_bonds + 127) / 128;
    const int gA = (n_atoms + 127) / 128;

    for (int g = 0; g < 2; g++) {
        float* mol_g = mol + g * (NMOLS * HDIM);
        const __half* Wib = Wbase_b + (3*g+0)*MS; const __half* Wis = Wbase_s + (3*g+0)*MS;
        const __half* Whb = Wbase_b + (3*g+1)*MS; const __half* Whs = Wbase_s + (3*g+1)*MS;
        const __half* Wob = Wbase_b + (3*g+2)*MS; const __half* Wos = Wbase_s + (3*g+2)*MS;

        // nih = fbonds @ Wi^T ; msgA = relu(nih)   (Kd=88, nk=6)
        h16_gemm_kernel<0><<<gB, 512, SMEM_BYTES>>>(
            fbonds[g], nullptr, Wib, Wis, nullptr, nullptr,
            nih, msgA, n_bonds, 6, 88, max_nei);

        // 3 MP iterations (K=256, nk=16), msg ping-pongs
        float* bufs[2] = { msgA, msgB };
        int cur = 0;
        for (int d = 0; d < 3; d++) {
            h16_gemm_kernel<1><<<gB, 512, SMEM_BYTES>>>(
                bufs[cur], bgraph[g], Whb, Whs, nih, nullptr,
                bufs[1 - cur], nullptr, n_bonds, 16, 256, max_nei);
            cur = 1 - cur;
        }

        // atom_h = relu([gather(256) | fatoms(82)] @ Wo'^T + bo)  (nk=22)
        h16_gemm_kernel<2><<<gA, 512, SMEM_BYTES>>>(
            bufs[cur], agraph[g], Wob, Wos, fatoms[g], bo[g],
            atom_h, nullptr, n_atoms, 22, 338, max_nei);

        segsum_kernel<<<NMOLS, 256>>>(atom_h, mol_idx[g], mol_g, n_atoms);
    }

    rxn_kernel<<<NMOLS, 256>>>(mol, mol + NMOLS * HDIM,
                               Wrh, brh, Wro, bro, (float*)d_out);
}